// round 1
// baseline (speedup 1.0000x reference)
#include <cuda_runtime.h>
#include <math.h>

#define Q_CODES   4096
#define E_DIM     256
#define BM        64          // rows per block
#define BQ        64          // codes per tile
#define BK        32          // k chunk
#define XS_STRIDE 264         // 256 + 8 pad (1056 B, 16B aligned)

__device__ int   g_idx_buf[32768];
__device__ float g_w2[Q_CODES];

// ---------------------------------------------------------------------------
// Kernel A: w2[q] = sum_k w[q][k]^2   (one warp per code)
// ---------------------------------------------------------------------------
__global__ void w2_kernel(const float* __restrict__ w) {
    int warp = (blockIdx.x * blockDim.x + threadIdx.x) >> 5;
    int lane = threadIdx.x & 31;
    if (warp >= Q_CODES) return;
    const float* row = w + (size_t)warp * E_DIM;
    float s = 0.f;
    #pragma unroll
    for (int k = lane; k < E_DIM; k += 32) { float v = row[k]; s = fmaf(v, v, s); }
    #pragma unroll
    for (int off = 16; off; off >>= 1) s += __shfl_down_sync(0xffffffffu, s, off);
    if (lane == 0) g_w2[warp] = s;
}

// ---------------------------------------------------------------------------
// Kernel B: per-row argmin over all 4096 codes of (x2 - 2*dot) + w2
// Block: 256 threads, 64 rows. tx = tid&15 (codes), ty = tid>>4 (rows).
// Each thread: 4 rows x 4 codes micro-tile.
// ---------------------------------------------------------------------------
__global__ __launch_bounds__(256, 2)
void vq_argmin_kernel(const float* __restrict__ x,
                      const float* __restrict__ w,
                      float* __restrict__ out_idx_f) {
    extern __shared__ float smem[];
    float* xs  = smem;                         // [BM][XS_STRIDE]
    float* ws  = smem + BM * XS_STRIDE;        // [BK][BQ] (k-major)
    float* x2s = ws + BK * BQ;                 // [BM]

    const int tid = threadIdx.x;
    const int tx  = tid & 15;
    const int ty  = tid >> 4;
    const int rowBase = blockIdx.x * BM;

    // ---- load x tile (64 rows x 256 floats), coalesced float4 along k ----
    const float4* xg = (const float4*)(x + (size_t)rowBase * E_DIM);
    #pragma unroll
    for (int i = tid; i < BM * (E_DIM / 4); i += 256) {
        int r  = i >> 6;            // / 64 float4s per row
        int k4 = i & 63;
        float4 v = xg[r * 64 + k4];
        *(float4*)&xs[r * XS_STRIDE + k4 * 4] = v;
    }
    __syncthreads();

    // ---- x2 per row (sequential fp32 accumulation) ----
    if (tid < BM) {
        const float* xr = &xs[tid * XS_STRIDE];
        float s = 0.f;
        for (int k = 0; k < E_DIM; ++k) s = fmaf(xr[k], xr[k], s);
        x2s[tid] = s;
    }
    __syncthreads();

    float a2[4];
    #pragma unroll
    for (int i = 0; i < 4; ++i) a2[i] = x2s[ty * 4 + i];

    float bestD[4];
    int   bestI[4];
    #pragma unroll
    for (int i = 0; i < 4; ++i) { bestD[i] = INFINITY; bestI[i] = 0; }

    const int nTiles  = Q_CODES / BQ;   // 64
    const int nChunks = E_DIM / BK;     // 8

    for (int qt = 0; qt < nTiles; ++qt) {
        const int codeBase = qt * BQ;
        const float4* wg = (const float4*)(w + (size_t)codeBase * E_DIM);

        float acc[4][4];
        #pragma unroll
        for (int i = 0; i < 4; ++i)
            #pragma unroll
            for (int j = 0; j < 4; ++j) acc[i][j] = 0.f;

        // prefetch chunk 0: per thread 2 float4s. f = tid + 256*i,
        // code = f>>3 (0..63), kq = f&7 (float4 index within 32-k chunk)
        float4 pre[2];
        #pragma unroll
        for (int i = 0; i < 2; ++i) {
            int f = tid + 256 * i;
            pre[i] = wg[(f >> 3) * 64 + (f & 7)];
        }

        for (int kc = 0; kc < nChunks; ++kc) {
            __syncthreads();
            // store prefetched chunk to smem, transposed to k-major
            #pragma unroll
            for (int i = 0; i < 2; ++i) {
                int f = tid + 256 * i;
                int code = f >> 3;
                int kq   = f & 7;
                ws[(kq * 4 + 0) * BQ + code] = pre[i].x;
                ws[(kq * 4 + 1) * BQ + code] = pre[i].y;
                ws[(kq * 4 + 2) * BQ + code] = pre[i].z;
                ws[(kq * 4 + 3) * BQ + code] = pre[i].w;
            }
            __syncthreads();
            // prefetch next chunk (hides L2 latency under the FFMA block)
            if (kc + 1 < nChunks) {
                #pragma unroll
                for (int i = 0; i < 2; ++i) {
                    int f = tid + 256 * i;
                    pre[i] = wg[(f >> 3) * 64 + (kc + 1) * 8 + (f & 7)];
                }
            }
            const int k0 = kc * BK;
            #pragma unroll
            for (int kk = 0; kk < BK; ++kk) {
                float a0 = xs[(ty * 4 + 0) * XS_STRIDE + k0 + kk];
                float a1 = xs[(ty * 4 + 1) * XS_STRIDE + k0 + kk];
                float a2v = xs[(ty * 4 + 2) * XS_STRIDE + k0 + kk];
                float a3 = xs[(ty * 4 + 3) * XS_STRIDE + k0 + kk];
                float4 bv = *(const float4*)&ws[kk * BQ + tx * 4];
                acc[0][0] = fmaf(a0, bv.x, acc[0][0]);
                acc[0][1] = fmaf(a0, bv.y, acc[0][1]);
                acc[0][2] = fmaf(a0, bv.z, acc[0][2]);
                acc[0][3] = fmaf(a0, bv.w, acc[0][3]);
                acc[1][0] = fmaf(a1, bv.x, acc[1][0]);
                acc[1][1] = fmaf(a1, bv.y, acc[1][1]);
                acc[1][2] = fmaf(a1, bv.z, acc[1][2]);
                acc[1][3] = fmaf(a1, bv.w, acc[1][3]);
                acc[2][0] = fmaf(a2v, bv.x, acc[2][0]);
                acc[2][1] = fmaf(a2v, bv.y, acc[2][1]);
                acc[2][2] = fmaf(a2v, bv.z, acc[2][2]);
                acc[2][3] = fmaf(a2v, bv.w, acc[2][3]);
                acc[3][0] = fmaf(a3, bv.x, acc[3][0]);
                acc[3][1] = fmaf(a3, bv.y, acc[3][1]);
                acc[3][2] = fmaf(a3, bv.z, acc[3][2]);
                acc[3][3] = fmaf(a3, bv.w, acc[3][3]);
            }
        }

        // epilogue: dist = fl(fl(x2 - 2*dot) + w2), running min (ties -> lower idx
        // automatic since codes visited in increasing order with strict <)
        #pragma unroll
        for (int j = 0; j < 4; ++j) {
            int code = codeBase + tx * 4 + j;
            float w2v = __ldg(&g_w2[code]);
            #pragma unroll
            for (int i = 0; i < 4; ++i) {
                float t = fmaf(-2.0f, acc[i][j], a2[i]);  // == fl(x2 - 2*dot)
                float d = t + w2v;
                if (d < bestD[i]) { bestD[i] = d; bestI[i] = code; }
            }
        }
    }

    // ---- cross-thread reduction over the 16 tx lanes of each row ----
    #pragma unroll
    for (int i = 0; i < 4; ++i) {
        float d  = bestD[i];
        int   bi = bestI[i];
        #pragma unroll
        for (int off = 8; off; off >>= 1) {
            float d2 = __shfl_down_sync(0xffffffffu, d, off, 16);
            int   i2 = __shfl_down_sync(0xffffffffu, bi, off, 16);
            if (d2 < d || (d2 == d && i2 < bi)) { d = d2; bi = i2; }
        }
        if (tx == 0) {
            int row = rowBase + ty * 4 + i;
            g_idx_buf[row] = bi;
            out_idx_f[row] = (float)bi;
        }
    }
}

// ---------------------------------------------------------------------------
// Kernel C: q_data[row] = weight[idx[row]]  (coalesced gather)
// ---------------------------------------------------------------------------
__global__ void gather_kernel(const float* __restrict__ w, float* __restrict__ out) {
    int row = blockIdx.x;
    int idx = g_idx_buf[row];
    const float4* src = (const float4*)(w + (size_t)idx * E_DIM);
    float4*       dst = (float4*)(out + (size_t)row * E_DIM);
    dst[threadIdx.x] = src[threadIdx.x];   // 64 threads x float4 = 256 floats
}

// ---------------------------------------------------------------------------
extern "C" void kernel_launch(void* const* d_in, const int* in_sizes, int n_in,
                              void* d_out, int out_size) {
    const float* x = (const float*)d_in[0];
    const float* w = (const float*)d_in[1];
    int rows = in_sizes[0] / E_DIM;            // 32768

    float* out      = (float*)d_out;
    float* out_idx  = out + (size_t)rows * E_DIM;

    static const int smem_bytes = (BM * XS_STRIDE + BK * BQ + BM) * (int)sizeof(float);
    cudaFuncSetAttribute(vq_argmin_kernel,
                         cudaFuncAttributeMaxDynamicSharedMemorySize, smem_bytes);

    w2_kernel<<<(Q_CODES * 32 + 255) / 256, 256>>>(w);
    vq_argmin_kernel<<<rows / BM, 256, smem_bytes>>>(x, w, out_idx);
    gather_kernel<<<rows, 64>>>(w, out);
}

// round 7
// speedup vs baseline: 2.5697x; 2.5697x over previous
#include <cuda_runtime.h>
#include <cuda_fp16.h>
#include <math.h>
#include <stdint.h>

#define Q_CODES   4096
#define E_DIM     256
#define ROWS_TOT  32768

#define BM        128     // rows per CTA (approx pass)
#define BN        128     // codes per tile
#define KCH       64      // k per chunk
#define NTILES    (Q_CODES / BN)        // 32
#define NCH       (E_DIM / KCH)         // 4
#define NSTEPS    (NTILES * NCH)        // 128

#define MARGIN    2.5e-4f               // >= 4x (2*maxerr); grid-dominated bound

// smem byte offsets (approx kernel)
#define XSH_OFF   0                     // 128 x 264 halves (hi)  = 67584
#define XSL_OFF   67584                 // lo                     = 67584
#define BST0_OFF  135168                // stage0: Bh 18432 + Bl 18432
#define BST1_OFF  172032                // stage1
#define W2S_OFF   208896                // 4096 floats = 16384
#define SREDB_OFF 225280                // 128 u64 = 1024
#define SREDS_OFF 226304                // 128 u32 = 512
#define SMEM_TOTAL 226816

#define BS_ROW_BYTES 144                // 72 halves per w row (64+8 pad)
#define B_TYPE_BYTES 18432              // 128*144

// device scratch
__device__ __half g_xh[ROWS_TOT * E_DIM];
__device__ __half g_xl[ROWS_TOT * E_DIM];
__device__ __half g_wh[Q_CODES * E_DIM];   // scaled by 1024
__device__ __half g_wl[Q_CODES * E_DIM];   // scaled by 1024
__device__ float  g_x2[ROWS_TOT];
__device__ float  g_w2[Q_CODES];
__device__ int    g_bestI[ROWS_TOT];
__device__ int    g_flag[ROWS_TOT];
__device__ int    g_flagrows[ROWS_TOT];
__device__ int    g_nflag;
__device__ unsigned long long g_red[ROWS_TOT];

// ---------------------------------------------------------------------------
__device__ __forceinline__ uint32_t smem_u32(const void* p) {
    uint32_t a;
    asm("{ .reg .u64 t; cvta.to.shared.u64 t, %1; cvt.u32.u64 %0, t; }" : "=r"(a) : "l"(p));
    return a;
}
#define CP_ASYNC16(dst, src) \
    asm volatile("cp.async.cg.shared.global [%0], [%1], 16;" :: "r"(dst), "l"(src))
#define CP_COMMIT() asm volatile("cp.async.commit_group;" ::: "memory")
#define CP_WAIT1()  asm volatile("cp.async.wait_group 1;" ::: "memory")
#define CP_WAIT0()  asm volatile("cp.async.wait_group 0;" ::: "memory")

#define LDMATRIX_X4(r0, r1, r2, r3, addr) \
    asm volatile("ldmatrix.sync.aligned.m8n8.x4.shared.b16 {%0,%1,%2,%3}, [%4];" \
                 : "=r"(r0), "=r"(r1), "=r"(r2), "=r"(r3) : "r"(addr))

__device__ __forceinline__ void mma16816(float* c, const uint32_t* a, const uint32_t* b) {
    asm volatile(
        "mma.sync.aligned.m16n8k16.row.col.f32.f16.f16.f32 "
        "{%0,%1,%2,%3}, {%4,%5,%6,%7}, {%8,%9}, {%0,%1,%2,%3};"
        : "+f"(c[0]), "+f"(c[1]), "+f"(c[2]), "+f"(c[3])
        : "r"(a[0]), "r"(a[1]), "r"(a[2]), "r"(a[3]), "r"(b[0]), "r"(b[1]));
}

// ---------------------------------------------------------------------------
// split: fp32 -> fp16 hi/lo (w pre-scaled by 1024 so lo stays fp16-normal)
// ---------------------------------------------------------------------------
__global__ void split_kernel(const float* __restrict__ src, __half* __restrict__ hi,
                             __half* __restrict__ lo, int n, float scale) {
    int i = blockIdx.x * blockDim.x + threadIdx.x;
    if (i >= n) return;
    float v = src[i] * scale;            // power-of-2 scale -> exact
    __half h = __float2half_rn(v);
    float r = v - __half2float(h);       // exact in fp32
    hi[i] = h;
    lo[i] = __float2half_rn(r);
}

// w2 / x2: identical numerics to the R0 kernel that passed
__global__ void w2_kernel(const float* __restrict__ w) {
    int warp = (blockIdx.x * blockDim.x + threadIdx.x) >> 5;
    int lane = threadIdx.x & 31;
    if (warp >= Q_CODES) return;
    const float* row = w + (size_t)warp * E_DIM;
    float s = 0.f;
    #pragma unroll
    for (int k = lane; k < E_DIM; k += 32) { float v = row[k]; s = fmaf(v, v, s); }
    #pragma unroll
    for (int off = 16; off; off >>= 1) s += __shfl_down_sync(0xffffffffu, s, off);
    if (lane == 0) g_w2[warp] = s;
}
__global__ void x2_kernel(const float* __restrict__ x) {
    __shared__ float xs[8 * E_DIM];
    int base = blockIdx.x * 8 * E_DIM;
    for (int i = threadIdx.x; i < 8 * E_DIM; i += 256) xs[i] = x[base + i];
    __syncthreads();
    if (threadIdx.x < 8) {
        const float* r = &xs[threadIdx.x * E_DIM];
        float s = 0.f;
        for (int k = 0; k < E_DIM; ++k) s = fmaf(r[k], r[k], s);
        g_x2[blockIdx.x * 8 + threadIdx.x] = s;
    }
}

// ---------------------------------------------------------------------------
// issue one B chunk (global step s) into its stage buffer via cp.async
// ---------------------------------------------------------------------------
__device__ __forceinline__ void issue_chunk(uint32_t smem_u, int s, int tid) {
    const int t = s >> 2, c = s & 3;
    const int codeBase = t * BN;
    const uint32_t bst = smem_u + ((s & 1) ? BST1_OFF : BST0_OFF);
    const __half* srcH = g_wh + (size_t)codeBase * E_DIM + c * KCH;
    const __half* srcL = g_wl + (size_t)codeBase * E_DIM + c * KCH;
    #pragma unroll
    for (int it = 0; it < 4; ++it) {
        int i = tid + it * 256;          // 0..1023
        int row = i >> 3, q = i & 7;     // q = 16B unit within 64 halves
        uint32_t dst = bst + (uint32_t)(row * BS_ROW_BYTES + q * 16);
        CP_ASYNC16(dst, (const void*)(srcH + row * E_DIM + q * 8));
        CP_ASYNC16(dst + B_TYPE_BYTES, (const void*)(srcL + row * E_DIM + q * 8));
    }
}

// ---------------------------------------------------------------------------
// approx pass: 3x-fp16 mma.sync GEMM + argmin with best AND second-best.
// Writes per-row g_bestI and g_flag (second-best within MARGIN of best).
// ---------------------------------------------------------------------------
__global__ __launch_bounds__(256, 1)
void vq_kernel() {
    extern __shared__ __align__(128) char smem[];
    const uint32_t smem_u = smem_u32(smem);
    float* w2s = (float*)(smem + W2S_OFF);
    unsigned long long* sredB = (unsigned long long*)(smem + SREDB_OFF);
    unsigned int*       sredS = (unsigned int*)(smem + SREDS_OFF);

    const int tid  = threadIdx.x;
    const int lane = tid & 31;
    const int wid  = tid >> 5;
    const int wm   = wid >> 2;          // 0..1
    const int wn   = wid & 3;           // 0..3
    const int rowBase = blockIdx.x * BM;

    issue_chunk(smem_u, 0, tid);
    CP_COMMIT();

    // resident A: 128 rows x 256 halves, hi+lo, row stride 528B
    {
        const uint4* gh = (const uint4*)(g_xh + (size_t)rowBase * E_DIM);
        const uint4* gl = (const uint4*)(g_xl + (size_t)rowBase * E_DIM);
        #pragma unroll
        for (int it = 0; it < 16; ++it) {
            int i = tid + it * 256;
            int r = i >> 5, q = i & 31;
            *(uint4*)(smem + XSH_OFF + r * 528 + q * 16) = gh[r * 32 + q];
            *(uint4*)(smem + XSL_OFF + r * 528 + q * 16) = gl[r * 32 + q];
        }
    }
    #pragma unroll
    for (int it = 0; it < 16; ++it) w2s[tid + it * 256] = g_w2[tid + it * 256];
    if (tid < BM) { sredB[tid] = 0xFFFFFFFFFFFFFFFFull; sredS[tid] = 0xFFFFFFFFu; }

    float x2r[8];
    #pragma unroll
    for (int mf = 0; mf < 4; ++mf)
        #pragma unroll
        for (int h = 0; h < 2; ++h)
            x2r[mf * 2 + h] = g_x2[rowBase + wm * 64 + mf * 16 + h * 8 + (lane >> 2)];

    float bestD[8], secD[8];
    int   bestI[8];
    #pragma unroll
    for (int i = 0; i < 8; ++i) { bestD[i] = INFINITY; secD[i] = INFINITY; bestI[i] = 0; }

    float acc[4][4][4];

    for (int t = 0; t < NTILES; ++t) {
        #pragma unroll
        for (int mf = 0; mf < 4; ++mf)
            #pragma unroll
            for (int nf = 0; nf < 4; ++nf)
                #pragma unroll
                for (int e = 0; e < 4; ++e) acc[mf][nf][e] = 0.f;

        for (int c = 0; c < NCH; ++c) {
            const int s = t * NCH + c;
            if (s + 1 < NSTEPS) {
                issue_chunk(smem_u, s + 1, tid);
                CP_COMMIT();
                CP_WAIT1();
            } else {
                CP_WAIT0();
            }
            __syncthreads();

            const uint32_t bst = smem_u + ((s & 1) ? BST1_OFF : BST0_OFF);
            const int kglob0 = c * KCH;

            #pragma unroll
            for (int kk = 0; kk < 4; ++kk) {
                const int kg = kglob0 + kk * 16;
                const int kl = kk * 16;

                uint32_t Ah[4][4], Al[4][4], Bh[4][2], Bl[4][2];
                #pragma unroll
                for (int mf = 0; mf < 4; ++mf) {
                    uint32_t off = (uint32_t)((wm * 64 + mf * 16 + (lane & 15)) * 528
                                              + (kg + ((lane >> 4) << 3)) * 2);
                    LDMATRIX_X4(Ah[mf][0], Ah[mf][1], Ah[mf][2], Ah[mf][3], smem_u + XSH_OFF + off);
                    LDMATRIX_X4(Al[mf][0], Al[mf][1], Al[mf][2], Al[mf][3], smem_u + XSL_OFF + off);
                }
                #pragma unroll
                for (int p = 0; p < 2; ++p) {
                    uint32_t n = (uint32_t)(wn * 32 + p * 16 + (lane & 7) + ((lane >> 4) << 3));
                    uint32_t off = n * BS_ROW_BYTES + (uint32_t)((kl + (((lane >> 3) & 1) << 3)) * 2);
                    LDMATRIX_X4(Bh[p*2][0], Bh[p*2][1], Bh[p*2+1][0], Bh[p*2+1][1], bst + off);
                    LDMATRIX_X4(Bl[p*2][0], Bl[p*2][1], Bl[p*2+1][0], Bl[p*2+1][1],
                                bst + B_TYPE_BYTES + off);
                }
                #pragma unroll
                for (int mf = 0; mf < 4; ++mf)
                    #pragma unroll
                    for (int nf = 0; nf < 4; ++nf) mma16816(acc[mf][nf], Ah[mf], Bh[nf]);
                #pragma unroll
                for (int mf = 0; mf < 4; ++mf)
                    #pragma unroll
                    for (int nf = 0; nf < 4; ++nf) mma16816(acc[mf][nf], Al[mf], Bh[nf]);
                #pragma unroll
                for (int mf = 0; mf < 4; ++mf)
                    #pragma unroll
                    for (int nf = 0; nf < 4; ++nf) mma16816(acc[mf][nf], Ah[mf], Bl[nf]);
            }
            __syncthreads();
        }

        // epilogue tile t: dist + running best/second (ascending code order)
        const int codeBase = t * BN + wn * 32;
        #pragma unroll
        for (int mf = 0; mf < 4; ++mf)
            #pragma unroll
            for (int h = 0; h < 2; ++h) {
                const int slot = mf * 2 + h;
                float x2v = x2r[slot];
                float d0 = bestD[slot], d1 = secD[slot];
                int   i0 = bestI[slot];
                #pragma unroll
                for (int nf = 0; nf < 4; ++nf)
                    #pragma unroll
                    for (int j = 0; j < 2; ++j) {
                        int code  = codeBase + nf * 8 + (lane & 3) * 2 + j;
                        float dot = acc[mf][nf][h * 2 + j] * 0.0009765625f;  // /1024 exact
                        float dv  = fmaf(-2.0f, dot, x2v) + w2s[code];
                        if (dv < d0)      { d1 = d0; d0 = dv; i0 = code; }
                        else if (dv < d1) { d1 = dv; }
                    }
                bestD[slot] = d0; secD[slot] = d1; bestI[slot] = i0;
            }
    }

    // reduction: best via packed atomicMin, then second-best across threads
    __syncthreads();
    #pragma unroll
    for (int i = 0; i < 8; ++i) {
        int rowLocal = wm * 64 + (i >> 1) * 16 + (i & 1) * 8 + (lane >> 2);
        unsigned long long pack =
            ((unsigned long long)__float_as_uint(bestD[i]) << 32) | (unsigned)bestI[i];
        atomicMin(&sredB[rowLocal], pack);
    }
    __syncthreads();
    #pragma unroll
    for (int i = 0; i < 8; ++i) {
        int rowLocal = wm * 64 + (i >> 1) * 16 + (i & 1) * 8 + (lane >> 2);
        unsigned winIdx = (unsigned)(sredB[rowLocal] & 0xffffffffull);
        float cand = ((unsigned)bestI[i] == winIdx) ? secD[i] : bestD[i];
        atomicMin(&sredS[rowLocal], __float_as_uint(cand));
    }
    __syncthreads();

    if (tid < BM) {
        unsigned long long bp = sredB[tid];
        float bd = __uint_as_float((unsigned)(bp >> 32));
        float sd = __uint_as_float(sredS[tid]);
        int   bi = (int)(bp & 0xffffffffull);
        int row = rowBase + tid;
        g_bestI[row] = bi;
        g_flag[row]  = (sd - bd <= MARGIN) ? 1 : 0;
    }
}

// ---------------------------------------------------------------------------
// reset + compact flagged rows
// ---------------------------------------------------------------------------
__global__ void reset_kernel() {
    if (blockIdx.x == 0 && threadIdx.x == 0) g_nflag = 0;
}
__global__ void compact_kernel() {
    int r = blockIdx.x * blockDim.x + threadIdx.x;
    if (r >= ROWS_TOT) return;
    if (g_flag[r]) {
        int p = atomicAdd(&g_nflag, 1);
        g_flagrows[p] = r;
        g_red[r] = 0xFFFFFFFFFFFFFFFFull;
    }
}

// ---------------------------------------------------------------------------
// fallback: EXACT R0 numerics for flagged rows.
// work item = (group of 8 flagged rows) x (quarter of 1024 codes).
// per lane: one code per 32-code tile, sequential ascending-k fp32 FMA chain.
// ---------------------------------------------------------------------------
__global__ __launch_bounds__(256)
void fallback_kernel(const float* __restrict__ x, const float* __restrict__ w) {
    __shared__ float xs[8 * 264];
    __shared__ float ws[32 * 257];
    __shared__ int   s_rows[8];

    const int tid = threadIdx.x;
    const int ty  = tid >> 5;            // row within group (= warp)
    const int tx  = tid & 31;            // lane

    const int nflag  = g_nflag;
    const int nItems = ((nflag + 7) >> 3) * 4;

    for (int item = blockIdx.x; item < nItems; item += gridDim.x) {
        const int grp = item >> 2, quarter = item & 3;
        __syncthreads();                 // protect smem reuse across items
        if (tid < 8) {
            int ri = grp * 8 + tid;
            s_rows[tid] = (ri < nflag) ? g_flagrows[ri] : -1;
        }
        __syncthreads();
        const int myRow = s_rows[ty];

        if (myRow >= 0) {
            const float4* xg = (const float4*)(x + (size_t)myRow * E_DIM);
            *(float4*)&xs[ty * 264 + tx * 8]     = xg[tx * 2];
            *(float4*)&xs[ty * 264 + tx * 8 + 4] = xg[tx * 2 + 1];
        }
        const float x2v = (myRow >= 0) ? g_x2[myRow] : 0.f;
        float bd = INFINITY;
        int   bi = 0;

        for (int ctile = 0; ctile < 32; ++ctile) {
            const int cb = quarter * 1024 + ctile * 32;
            __syncthreads();
            // stage 32 codes x 256 floats, stride 257 (conflict-free compute reads)
            {
                const float* wg = w + (size_t)cb * E_DIM;
                #pragma unroll
                for (int it = 0; it < 32; ++it) {
                    int i = tid + it * 256;          // 0..8191
                    ws[(i >> 8) * 257 + (i & 255)] = wg[i];
                }
            }
            __syncthreads();

            // exact R0 chain: ascending k, single fp32 FMA chain
            const float* xr = &xs[ty * 264];
            const float* wr = &ws[tx * 257];
            float acc = 0.f;
            #pragma unroll 8
            for (int k = 0; k < E_DIM; ++k) acc = fmaf(xr[k], wr[k], acc);

            float tq = fmaf(-2.0f, acc, x2v);
            float d  = tq + __ldg(&g_w2[cb + tx]);
            int code = cb + tx;
            if (d < bd) { bd = d; bi = code; }
        }

        // warp lexicographic (d, idx) reduction; one atomic per row per item
        #pragma unroll
        for (int off = 16; off; off >>= 1) {
            float d2 = __shfl_down_sync(0xffffffffu, bd, off);
            int   i2 = __shfl_down_sync(0xffffffffu, bi, off);
            if (d2 < bd || (d2 == bd && i2 < bi)) { bd = d2; bi = i2; }
        }
        if (tx == 0 && myRow >= 0) {
            unsigned long long pack =
                ((unsigned long long)__float_as_uint(bd) << 32) | (unsigned)bi;
            atomicMin(&g_red[myRow], pack);
        }
    }
}

// ---------------------------------------------------------------------------
// gather + final idx selection
// ---------------------------------------------------------------------------
__global__ void gather_kernel(const float* __restrict__ w, float* __restrict__ out,
                              float* __restrict__ out_idx_f) {
    int row = blockIdx.x;
    int idx = g_flag[row] ? (int)(g_red[row] & 0xffffffffull) : g_bestI[row];
    const float4* src = (const float4*)(w + (size_t)idx * E_DIM);
    float4*       dst = (float4*)(out + (size_t)row * E_DIM);
    dst[threadIdx.x] = src[threadIdx.x];
    if (threadIdx.x == 0) out_idx_f[row] = (float)idx;
}

// ---------------------------------------------------------------------------
extern "C" void kernel_launch(void* const* d_in, const int* in_sizes, int n_in,
                              void* d_out, int out_size) {
    const float* x = (const float*)d_in[0];
    const float* w = (const float*)d_in[1];
    int rows = in_sizes[0] / E_DIM;        // 32768

    float* out     = (float*)d_out;
    float* out_idx = out + (size_t)rows * E_DIM;

    __half *xh, *xl, *wh, *wl;
    cudaGetSymbolAddress((void**)&xh, g_xh);
    cudaGetSymbolAddress((void**)&xl, g_xl);
    cudaGetSymbolAddress((void**)&wh, g_wh);
    cudaGetSymbolAddress((void**)&wl, g_wl);

    cudaFuncSetAttribute(vq_kernel,
                         cudaFuncAttributeMaxDynamicSharedMemorySize, SMEM_TOTAL);

    int nx = rows * E_DIM;
    int nw = Q_CODES * E_DIM;
    split_kernel<<<(nx + 255) / 256, 256>>>(x, xh, xl, nx, 1.0f);
    split_kernel<<<(nw + 255) / 256, 256>>>(w, wh, wl, nw, 1024.0f);
    w2_kernel<<<(Q_CODES * 32 + 255) / 256, 256>>>(w);
    x2_kernel<<<rows / 8, 256>>>(x);
    vq_kernel<<<rows / BM, 256, SMEM_TOTAL>>>();
    reset_kernel<<<1, 32>>>();
    compact_kernel<<<(ROWS_TOT + 255) / 256, 256>>>();
    fallback_kernel<<<512, 256>>>(x, w);
    gather_kernel<<<rows, 64>>>(w, out, out_idx);
}

// round 9
// speedup vs baseline: 4.9275x; 1.9175x over previous
#include <cuda_runtime.h>
#include <cuda_fp16.h>
#include <math.h>
#include <stdint.h>

#define Q_CODES   4096
#define E_DIM     256
#define ROWS_TOT  32768

#define BM        128     // rows per CTA (vq pass)
#define BN        128     // codes per tile
#define KCH       64      // k per chunk
#define NTILES    (Q_CODES / BN)        // 32
#define NCH       (E_DIM / KCH)         // 4
#define NSTEPS    (NTILES * NCH)        // 128

#define M_FLAG    4e-4f   // flag margin  (bound 2*maxerr1 ~ 2e-4, 2x safety)
#define M_COLL    4e-4f   // refine collect margin (bound maxerr1+maxerr3 ~ 1.7e-4)

// ---- vq smem offsets (hi-only B) ----
#define XSH_OFF   0                     // 128 x 528B = 67584
#define BST0_OFF  67584                 // 128 codes x 144B = 18432
#define BST1_OFF  86016
#define W2S_OFF   104448                // 4096 floats
#define SREDB_OFF 120832                // 128 u64
#define SREDS_OFF 121856                // 128 u32
#define VQ_SMEM   122368

// ---- refine smem offsets ----
#define RXH_OFF   0                     // 32 x 528 = 16896
#define RXL_OFF   16896
#define RB0_OFF   33792                 // hi 18432 + lo 18432
#define RB1_OFF   70656
#define RW2_OFF   107520                // 1024 floats
#define RROW_OFF  111616                // 32 ints
#define RF_SMEM   111744

#define BS_ROW_BYTES 144
#define B_TYPE_BYTES 18432

// device scratch
__device__ __half g_xh[ROWS_TOT * E_DIM];
__device__ __half g_xl[ROWS_TOT * E_DIM];
__device__ __half g_wh[Q_CODES * E_DIM];   // scaled by 1024
__device__ __half g_wl[Q_CODES * E_DIM];   // scaled by 1024
__device__ __half g_xh2[ROWS_TOT * E_DIM]; // compacted flagged rows
__device__ __half g_xl2[ROWS_TOT * E_DIM];
__device__ float  g_x2[ROWS_TOT];
__device__ float  g_w2[Q_CODES];
__device__ float  g_bestD[ROWS_TOT];
__device__ int    g_bestI[ROWS_TOT];
__device__ int    g_flag[ROWS_TOT];
__device__ int    g_flagrows[ROWS_TOT];
__device__ int    g_nflag;
__device__ unsigned long long g_red[ROWS_TOT];

// ---------------------------------------------------------------------------
__device__ __forceinline__ uint32_t smem_u32(const void* p) {
    uint32_t a;
    asm("{ .reg .u64 t; cvta.to.shared.u64 t, %1; cvt.u32.u64 %0, t; }" : "=r"(a) : "l"(p));
    return a;
}
#define CP_ASYNC16(dst, src) \
    asm volatile("cp.async.cg.shared.global [%0], [%1], 16;" :: "r"(dst), "l"(src))
#define CP_COMMIT() asm volatile("cp.async.commit_group;" ::: "memory")
#define CP_WAIT1()  asm volatile("cp.async.wait_group 1;" ::: "memory")
#define CP_WAIT0()  asm volatile("cp.async.wait_group 0;" ::: "memory")

#define LDMATRIX_X4(r0, r1, r2, r3, addr) \
    asm volatile("ldmatrix.sync.aligned.m8n8.x4.shared.b16 {%0,%1,%2,%3}, [%4];" \
                 : "=r"(r0), "=r"(r1), "=r"(r2), "=r"(r3) : "r"(addr))

__device__ __forceinline__ void mma16816(float* c, const uint32_t* a, const uint32_t* b) {
    asm volatile(
        "mma.sync.aligned.m16n8k16.row.col.f32.f16.f16.f32 "
        "{%0,%1,%2,%3}, {%4,%5,%6,%7}, {%8,%9}, {%0,%1,%2,%3};"
        : "+f"(c[0]), "+f"(c[1]), "+f"(c[2]), "+f"(c[3])
        : "r"(a[0]), "r"(a[1]), "r"(a[2]), "r"(a[3]), "r"(b[0]), "r"(b[1]));
}

// exact R0-numerics distance (ascending-k fp32 FMA chain)
__device__ __forceinline__ float exact_dist(const float* __restrict__ x,
                                            const float* __restrict__ w,
                                            int row, int code) {
    const float* xr = x + (size_t)row * E_DIM;
    const float* wr = w + (size_t)code * E_DIM;
    float acc = 0.f;
    #pragma unroll 8
    for (int k = 0; k < E_DIM; ++k) acc = fmaf(__ldg(xr + k), __ldg(wr + k), acc);
    return fmaf(-2.0f, acc, g_x2[row]) + g_w2[code];
}

// ---------------------------------------------------------------------------
// fused split(x) + x2 : 32 rows per block
// ---------------------------------------------------------------------------
__global__ void splitx_x2_kernel(const float* __restrict__ x) {
    __shared__ float xs[32 * E_DIM];
    const int tid = threadIdx.x;
    const int base = blockIdx.x * 32 * E_DIM;
    #pragma unroll
    for (int it = 0; it < 32; ++it) {
        int i = tid + it * 256;
        xs[i] = x[base + i];
    }
    __syncthreads();
    #pragma unroll
    for (int it = 0; it < 32; ++it) {
        int i = tid + it * 256;
        float v = xs[i];
        __half h = __float2half_rn(v);
        g_xh[base + i] = h;
        g_xl[base + i] = __float2half_rn(v - __half2float(h));
    }
    if (tid < 32) {
        const float* r = &xs[tid * E_DIM];
        float s = 0.f;
        for (int k = 0; k < E_DIM; ++k) s = fmaf(r[k], r[k], s);
        g_x2[blockIdx.x * 32 + tid] = s;
    }
}

// ---------------------------------------------------------------------------
// fused split(w, scale 1024) + w2 : warp per code (w2 numerics == R0)
// ---------------------------------------------------------------------------
__global__ void splitw_w2_kernel(const float* __restrict__ w) {
    int code = (blockIdx.x * blockDim.x + threadIdx.x) >> 5;
    int lane = threadIdx.x & 31;
    if (code >= Q_CODES) return;
    const float* row = w + (size_t)code * E_DIM;
    float v[8];
    float s = 0.f;
    #pragma unroll
    for (int j = 0; j < 8; ++j) {
        v[j] = row[lane + 32 * j];
        s = fmaf(v[j], v[j], s);
    }
    #pragma unroll
    for (int off = 16; off; off >>= 1) s += __shfl_down_sync(0xffffffffu, s, off);
    if (lane == 0) g_w2[code] = s;
    #pragma unroll
    for (int j = 0; j < 8; ++j) {
        float sv = v[j] * 1024.0f;                 // exact
        __half h = __float2half_rn(sv);
        g_wh[(size_t)code * E_DIM + lane + 32 * j] = h;
        g_wl[(size_t)code * E_DIM + lane + 32 * j] = __float2half_rn(sv - __half2float(h));
    }
}

__global__ void reset_kernel() { if (threadIdx.x == 0) g_nflag = 0; }
__global__ void pad_kernel() {}

// ---------------------------------------------------------------------------
// vq B chunk (hi only)
// ---------------------------------------------------------------------------
__device__ __forceinline__ void vq_issue_chunk(uint32_t smem_u, int s, int tid) {
    const int t = s >> 2, c = s & 3;
    const uint32_t bst = smem_u + ((s & 1) ? BST1_OFF : BST0_OFF);
    const __half* srcH = g_wh + (size_t)(t * BN) * E_DIM + c * KCH;
    #pragma unroll
    for (int it = 0; it < 4; ++it) {
        int i = tid + it * 256;          // 0..1023
        int row = i >> 3, q = i & 7;
        CP_ASYNC16(bst + (uint32_t)(row * BS_ROW_BYTES + q * 16),
                   (const void*)(srcH + row * E_DIM + q * 8));
    }
}

// ---------------------------------------------------------------------------
// vq pass: SINGLE-pass fp16 mma + best/second-best; writes bestI/bestD/flag
// ---------------------------------------------------------------------------
__global__ __launch_bounds__(256, 1)
void vq_kernel() {
    extern __shared__ __align__(128) char smem[];
    const uint32_t smem_u = smem_u32(smem);
    float* w2s = (float*)(smem + W2S_OFF);
    unsigned long long* sredB = (unsigned long long*)(smem + SREDB_OFF);
    unsigned int*       sredS = (unsigned int*)(smem + SREDS_OFF);

    const int tid  = threadIdx.x;
    const int lane = tid & 31;
    const int wid  = tid >> 5;
    const int wm   = wid >> 2;
    const int wn   = wid & 3;
    const int rowBase = blockIdx.x * BM;

    vq_issue_chunk(smem_u, 0, tid);
    CP_COMMIT();

    {   // resident A (hi only), row stride 528B
        const uint4* gh = (const uint4*)(g_xh + (size_t)rowBase * E_DIM);
        #pragma unroll
        for (int it = 0; it < 16; ++it) {
            int i = tid + it * 256;
            int r = i >> 5, q = i & 31;
            *(uint4*)(smem + XSH_OFF + r * 528 + q * 16) = gh[r * 32 + q];
        }
    }
    #pragma unroll
    for (int it = 0; it < 16; ++it) w2s[tid + it * 256] = g_w2[tid + it * 256];
    if (tid < BM) { sredB[tid] = 0xFFFFFFFFFFFFFFFFull; sredS[tid] = 0xFFFFFFFFu; }

    float x2r[8];
    #pragma unroll
    for (int mf = 0; mf < 4; ++mf)
        #pragma unroll
        for (int h = 0; h < 2; ++h)
            x2r[mf * 2 + h] = g_x2[rowBase + wm * 64 + mf * 16 + h * 8 + (lane >> 2)];

    float bestD[8], secD[8];
    int   bestI[8];
    #pragma unroll
    for (int i = 0; i < 8; ++i) { bestD[i] = INFINITY; secD[i] = INFINITY; bestI[i] = 0; }

    float acc[4][4][4];

    for (int t = 0; t < NTILES; ++t) {
        #pragma unroll
        for (int mf = 0; mf < 4; ++mf)
            #pragma unroll
            for (int nf = 0; nf < 4; ++nf)
                #pragma unroll
                for (int e = 0; e < 4; ++e) acc[mf][nf][e] = 0.f;

        for (int c = 0; c < NCH; ++c) {
            const int s = t * NCH + c;
            if (s + 1 < NSTEPS) { vq_issue_chunk(smem_u, s + 1, tid); CP_COMMIT(); CP_WAIT1(); }
            else                { CP_WAIT0(); }
            __syncthreads();

            const uint32_t bst = smem_u + ((s & 1) ? BST1_OFF : BST0_OFF);
            const int kglob0 = c * KCH;

            #pragma unroll
            for (int kk = 0; kk < 4; ++kk) {
                const int kg = kglob0 + kk * 16;
                const int kl = kk * 16;
                uint32_t Ah[4][4], Bh[4][2];
                #pragma unroll
                for (int mf = 0; mf < 4; ++mf) {
                    uint32_t off = (uint32_t)((wm * 64 + mf * 16 + (lane & 15)) * 528
                                              + (kg + ((lane >> 4) << 3)) * 2);
                    LDMATRIX_X4(Ah[mf][0], Ah[mf][1], Ah[mf][2], Ah[mf][3], smem_u + XSH_OFF + off);
                }
                #pragma unroll
                for (int p = 0; p < 2; ++p) {
                    uint32_t n = (uint32_t)(wn * 32 + p * 16 + (lane & 7) + ((lane >> 4) << 3));
                    uint32_t off = n * BS_ROW_BYTES + (uint32_t)((kl + (((lane >> 3) & 1) << 3)) * 2);
                    LDMATRIX_X4(Bh[p*2][0], Bh[p*2][1], Bh[p*2+1][0], Bh[p*2+1][1], bst + off);
                }
                #pragma unroll
                for (int mf = 0; mf < 4; ++mf)
                    #pragma unroll
                    for (int nf = 0; nf < 4; ++nf) mma16816(acc[mf][nf], Ah[mf], Bh[nf]);
            }
            __syncthreads();
        }

        const int codeBase = t * BN + wn * 32;
        #pragma unroll
        for (int mf = 0; mf < 4; ++mf)
            #pragma unroll
            for (int h = 0; h < 2; ++h) {
                const int slot = mf * 2 + h;
                float x2v = x2r[slot];
                float d0 = bestD[slot], d1 = secD[slot];
                int   i0 = bestI[slot];
                #pragma unroll
                for (int nf = 0; nf < 4; ++nf)
                    #pragma unroll
                    for (int j = 0; j < 2; ++j) {
                        int code  = codeBase + nf * 8 + (lane & 3) * 2 + j;
                        float dot = acc[mf][nf][h * 2 + j] * 0.0009765625f;
                        float dv  = fmaf(-2.0f, dot, x2v) + w2s[code];
                        if (dv < d0)      { d1 = d0; d0 = dv; i0 = code; }
                        else if (dv < d1) { d1 = dv; }
                    }
                bestD[slot] = d0; secD[slot] = d1; bestI[slot] = i0;
            }
    }

    __syncthreads();
    #pragma unroll
    for (int i = 0; i < 8; ++i) {
        int rowLocal = wm * 64 + (i >> 1) * 16 + (i & 1) * 8 + (lane >> 2);
        unsigned long long pack =
            ((unsigned long long)__float_as_uint(bestD[i]) << 32) | (unsigned)bestI[i];
        atomicMin(&sredB[rowLocal], pack);
    }
    __syncthreads();
    #pragma unroll
    for (int i = 0; i < 8; ++i) {
        int rowLocal = wm * 64 + (i >> 1) * 16 + (i & 1) * 8 + (lane >> 2);
        unsigned winIdx = (unsigned)(sredB[rowLocal] & 0xffffffffull);
        float cand = ((unsigned)bestI[i] == winIdx) ? secD[i] : bestD[i];
        atomicMin(&sredS[rowLocal], __float_as_uint(cand));
    }
    __syncthreads();

    if (tid < BM) {
        unsigned long long bp = sredB[tid];
        float bd = __uint_as_float((unsigned)(bp >> 32));
        float sd = __uint_as_float(sredS[tid]);
        int row = rowBase + tid;
        g_bestI[row] = (int)(bp & 0xffffffffull);
        g_bestD[row] = bd;
        g_flag[row]  = (sd - bd <= M_FLAG) ? 1 : 0;
    }
}

// ---------------------------------------------------------------------------
__global__ void compact_kernel() {
    int r = blockIdx.x * blockDim.x + threadIdx.x;
    if (r >= ROWS_TOT) return;
    if (g_flag[r]) {
        int p = atomicAdd(&g_nflag, 1);
        g_flagrows[p] = r;
        g_red[r] = 0xFFFFFFFFFFFFFFFFull;
    }
}
__global__ void copyrows_kernel() {
    const int nf = g_nflag;
    const int t = threadIdx.x;              // 64
    for (int p = blockIdx.x; p < nf; p += gridDim.x) {
        int row = g_flagrows[p];
        if (t < 32)
            ((uint4*)(g_xh2 + (size_t)p * E_DIM))[t] =
                ((const uint4*)(g_xh + (size_t)row * E_DIM))[t];
        else
            ((uint4*)(g_xl2 + (size_t)p * E_DIM))[t - 32] =
                ((const uint4*)(g_xl + (size_t)row * E_DIM))[t - 32];
    }
}

// ---------------------------------------------------------------------------
// refine B chunk (hi + lo)
// ---------------------------------------------------------------------------
__device__ __forceinline__ void rf_issue_chunk(uint32_t smem_u, int quarter, int s, int tid) {
    const int t = s >> 2, c = s & 3;
    const int codeBase = quarter * 1024 + t * BN;
    const uint32_t bst = smem_u + ((s & 1) ? RB1_OFF : RB0_OFF);
    const __half* srcH = g_wh + (size_t)codeBase * E_DIM + c * KCH;
    const __half* srcL = g_wl + (size_t)codeBase * E_DIM + c * KCH;
    #pragma unroll
    for (int it = 0; it < 4; ++it) {
        int i = tid + it * 256;
        int row = i >> 3, q = i & 7;
        uint32_t dst = bst + (uint32_t)(row * BS_ROW_BYTES + q * 16);
        CP_ASYNC16(dst, (const void*)(srcH + row * E_DIM + q * 8));
        CP_ASYNC16(dst + B_TYPE_BYTES, (const void*)(srcL + row * E_DIM + q * 8));
    }
}

// ---------------------------------------------------------------------------
// refine: flagged rows, 3-pass fp16 mma; candidates (dv <= bestD+M) -> exact
// item = (group of 32 flagged rows) x (quarter of codes). grid-stride.
// ---------------------------------------------------------------------------
__global__ __launch_bounds__(256, 1)
void refine_kernel(const float* __restrict__ x, const float* __restrict__ w) {
    extern __shared__ __align__(128) char smem[];
    const uint32_t smem_u = smem_u32(smem);
    float* w2q  = (float*)(smem + RW2_OFF);
    int*   srow = (int*)(smem + RROW_OFF);

    const int tid  = threadIdx.x;
    const int lane = tid & 31;
    const int wid  = tid >> 5;
    const int wm   = wid >> 2;          // 0..1 -> 16 rows each
    const int wn   = wid & 3;

    const int nflag  = g_nflag;
    const int nItems = ((nflag + 31) >> 5) * 4;

    for (int item = blockIdx.x; item < nItems; item += gridDim.x) {
        const int grp = item >> 2, quarter = item & 3;
        __syncthreads();                 // smem reuse across items

        rf_issue_chunk(smem_u, quarter, 0, tid);
        CP_COMMIT();

        // compacted A rows (clamp padding to last valid row; harmless dup)
        #pragma unroll
        for (int it = 0; it < 4; ++it) {
            int i = tid + it * 256;      // 0..1023
            int r = i >> 5, q = i & 31;
            int p = grp * 32 + r; if (p >= nflag) p = nflag - 1;
            *(uint4*)(smem + RXH_OFF + r * 528 + q * 16) =
                ((const uint4*)(g_xh2 + (size_t)p * E_DIM))[q];
            *(uint4*)(smem + RXL_OFF + r * 528 + q * 16) =
                ((const uint4*)(g_xl2 + (size_t)p * E_DIM))[q];
        }
        #pragma unroll
        for (int it = 0; it < 4; ++it)
            w2q[tid + it * 256] = g_w2[quarter * 1024 + tid + it * 256];
        if (tid < 32) {
            int p = grp * 32 + tid; if (p >= nflag) p = nflag - 1;
            srow[tid] = g_flagrows[p];
        }
        __syncthreads();

        // per-slot row info (h = 0,1)
        int   rid[2]; float x2v[2], thr[2];
        #pragma unroll
        for (int h = 0; h < 2; ++h) {
            int rl = wm * 16 + h * 8 + (lane >> 2);
            rid[h] = srow[rl];
            x2v[h] = g_x2[rid[h]];
            thr[h] = g_bestD[rid[h]] + M_COLL;
        }

        for (int t = 0; t < 8; ++t) {    // 8 tiles of 128 codes in this quarter
            float acc[4][4];
            #pragma unroll
            for (int nf = 0; nf < 4; ++nf)
                #pragma unroll
                for (int e = 0; e < 4; ++e) acc[nf][e] = 0.f;

            for (int c = 0; c < 4; ++c) {
                const int s = t * 4 + c;
                if (s + 1 < 32) { rf_issue_chunk(smem_u, quarter, s + 1, tid); CP_COMMIT(); CP_WAIT1(); }
                else            { CP_WAIT0(); }
                __syncthreads();

                const uint32_t bst = smem_u + ((s & 1) ? RB1_OFF : RB0_OFF);
                const int kglob0 = c * KCH;

                #pragma unroll
                for (int kk = 0; kk < 4; ++kk) {
                    const int kg = kglob0 + kk * 16;
                    const int kl = kk * 16;
                    uint32_t Ah[4], Al[4], Bh[4][2], Bl[4][2];
                    {
                        uint32_t off = (uint32_t)((wm * 16 + (lane & 15)) * 528
                                                  + (kg + ((lane >> 4) << 3)) * 2);
                        LDMATRIX_X4(Ah[0], Ah[1], Ah[2], Ah[3], smem_u + RXH_OFF + off);
                        LDMATRIX_X4(Al[0], Al[1], Al[2], Al[3], smem_u + RXL_OFF + off);
                    }
                    #pragma unroll
                    for (int p = 0; p < 2; ++p) {
                        uint32_t n = (uint32_t)(wn * 32 + p * 16 + (lane & 7) + ((lane >> 4) << 3));
                        uint32_t off = n * BS_ROW_BYTES + (uint32_t)((kl + (((lane >> 3) & 1) << 3)) * 2);
                        LDMATRIX_X4(Bh[p*2][0], Bh[p*2][1], Bh[p*2+1][0], Bh[p*2+1][1], bst + off);
                        LDMATRIX_X4(Bl[p*2][0], Bl[p*2][1], Bl[p*2+1][0], Bl[p*2+1][1],
                                    bst + B_TYPE_BYTES + off);
                    }
                    #pragma unroll
                    for (int nf = 0; nf < 4; ++nf) mma16816(acc[nf], Ah, Bh[nf]);
                    #pragma unroll
                    for (int nf = 0; nf < 4; ++nf) mma16816(acc[nf], Al, Bh[nf]);
                    #pragma unroll
                    for (int nf = 0; nf < 4; ++nf) mma16816(acc[nf], Ah, Bl[nf]);
                }
                __syncthreads();
            }

            // candidate collection + exact eval
            const int codeBase = quarter * 1024 + t * BN + wn * 32;
            #pragma unroll
            for (int h = 0; h < 2; ++h)
                #pragma unroll
                for (int nf = 0; nf < 4; ++nf)
                    #pragma unroll
                    for (int j = 0; j < 2; ++j) {
                        int code  = codeBase + nf * 8 + (lane & 3) * 2 + j;
                        float dot = acc[nf][h * 2 + j] * 0.0009765625f;
                        float dv  = fmaf(-2.0f, dot, x2v[h]) + w2q[t * BN + wn * 32 + nf * 8 + (lane & 3) * 2 + j];
                        if (dv <= thr[h]) {
                            float de = exact_dist(x, w, rid[h], code);
                            unsigned long long pack =
                                ((unsigned long long)__float_as_uint(de) << 32) | (unsigned)code;
                            atomicMin(&g_red[rid[h]], pack);
                        }
                    }
        }
    }
}

// ---------------------------------------------------------------------------
__global__ void gather_kernel(const float* __restrict__ w, float* __restrict__ out,
                              float* __restrict__ out_idx_f) {
    int row = blockIdx.x;
    int idx = g_flag[row] ? (int)(g_red[row] & 0xffffffffull) : g_bestI[row];
    const float4* src = (const float4*)(w + (size_t)idx * E_DIM);
    float4*       dst = (float4*)(out + (size_t)row * E_DIM);
    dst[threadIdx.x] = src[threadIdx.x];
    if (threadIdx.x == 0) out_idx_f[row] = (float)idx;
}

// ---------------------------------------------------------------------------
extern "C" void kernel_launch(void* const* d_in, const int* in_sizes, int n_in,
                              void* d_out, int out_size) {
    const float* x = (const float*)d_in[0];
    const float* w = (const float*)d_in[1];
    int rows = in_sizes[0] / E_DIM;        // 32768

    float* out     = (float*)d_out;
    float* out_idx = out + (size_t)rows * E_DIM;

    cudaFuncSetAttribute(vq_kernel,
                         cudaFuncAttributeMaxDynamicSharedMemorySize, VQ_SMEM);
    cudaFuncSetAttribute(refine_kernel,
                         cudaFuncAttributeMaxDynamicSharedMemorySize, RF_SMEM);

    splitx_x2_kernel<<<rows / 32, 256>>>(x);                  // 1
    splitw_w2_kernel<<<Q_CODES / 8, 256>>>(w);                // 2
    reset_kernel<<<1, 32>>>();                                // 3
    pad_kernel<<<1, 32>>>();                                  // 4
    pad_kernel<<<1, 32>>>();                                  // 5
    vq_kernel<<<rows / BM, 256, VQ_SMEM>>>();                 // 6  <- ncu -s 5 -c 1
    compact_kernel<<<(ROWS_TOT + 255) / 256, 256>>>();        // 7
    copyrows_kernel<<<1024, 64>>>();                          // 8
    refine_kernel<<<444, 256, RF_SMEM>>>(x, w);               // 9
    gather_kernel<<<rows, 64>>>(w, out, out_idx);             // 10
}

// round 11
// speedup vs baseline: 5.1100x; 1.0370x over previous
#include <cuda_runtime.h>
#include <cuda_fp16.h>
#include <math.h>
#include <stdint.h>

#define Q_CODES   4096
#define E_DIM     256
#define ROWS_TOT  32768

#define BM        128     // rows per CTA (vq pass)
#define BN        128     // codes per tile
#define KCH       64      // k per chunk
#define NTILES    (Q_CODES / BN)        // 32
#define NCH       (E_DIM / KCH)         // 4
#define NSTEPS    (NTILES * NCH)        // 128

#define M_FLAG    4e-4f   // flag margin  (bound 2*maxerr1 ~ 2e-4, 2x safety)
#define M_COLL    4e-4f   // refine collect margin (bound maxerr1+maxerr3 ~ 1.7e-4)

// ---- vq smem offsets (hi-only B) ----
#define XSH_OFF   0                     // 128 x 528B = 67584
#define BST0_OFF  67584                 // 128 codes x 144B = 18432
#define BST1_OFF  86016
#define W2S_OFF   104448                // 4096 floats
#define SREDB_OFF 120832                // 128 u64
#define SREDS_OFF 121856                // 128 u32
#define VQ_SMEM   122368

// ---- refine smem offsets ----
#define RXH_OFF   0                     // 32 x 528 = 16896
#define RXL_OFF   16896
#define RB0_OFF   33792                 // hi 18432 + lo 18432
#define RB1_OFF   70656
#define RW2_OFF   107520                // 1024 floats
#define RROW_OFF  111616                // 32 ints
#define RF_SMEM   111744

#define BS_ROW_BYTES 144
#define B_TYPE_BYTES 18432

// device scratch
__device__ __half g_xh[ROWS_TOT * E_DIM];
__device__ __half g_wh[Q_CODES * E_DIM];   // scaled by 1024
__device__ __half g_wl[Q_CODES * E_DIM];   // scaled by 1024
__device__ __half g_xh2[ROWS_TOT * E_DIM]; // compacted flagged rows (hi)
__device__ __half g_xl2[ROWS_TOT * E_DIM]; // compacted flagged rows (lo)
__device__ float  g_x2[ROWS_TOT];
__device__ float  g_w2[Q_CODES];
__device__ float  g_bestD[ROWS_TOT];
__device__ int    g_bestI[ROWS_TOT];
__device__ int    g_flag[ROWS_TOT];
__device__ int    g_flagrows[ROWS_TOT];
__device__ int    g_nflag;
__device__ unsigned long long g_red[ROWS_TOT];

// ---------------------------------------------------------------------------
__device__ __forceinline__ uint32_t smem_u32(const void* p) {
    uint32_t a;
    asm("{ .reg .u64 t; cvta.to.shared.u64 t, %1; cvt.u32.u64 %0, t; }" : "=r"(a) : "l"(p));
    return a;
}
#define CP_ASYNC16(dst, src) \
    asm volatile("cp.async.cg.shared.global [%0], [%1], 16;" :: "r"(dst), "l"(src))
#define CP_COMMIT() asm volatile("cp.async.commit_group;" ::: "memory")
#define CP_WAIT1()  asm volatile("cp.async.wait_group 1;" ::: "memory")
#define CP_WAIT0()  asm volatile("cp.async.wait_group 0;" ::: "memory")

#define LDMATRIX_X4(r0, r1, r2, r3, addr) \
    asm volatile("ldmatrix.sync.aligned.m8n8.x4.shared.b16 {%0,%1,%2,%3}, [%4];" \
                 : "=r"(r0), "=r"(r1), "=r"(r2), "=r"(r3) : "r"(addr))

__device__ __forceinline__ void mma16816(float* c, const uint32_t* a, const uint32_t* b) {
    asm volatile(
        "mma.sync.aligned.m16n8k16.row.col.f32.f16.f16.f32 "
        "{%0,%1,%2,%3}, {%4,%5,%6,%7}, {%8,%9}, {%0,%1,%2,%3};"
        : "+f"(c[0]), "+f"(c[1]), "+f"(c[2]), "+f"(c[3])
        : "r"(a[0]), "r"(a[1]), "r"(a[2]), "r"(a[3]), "r"(b[0]), "r"(b[1]));
}

// exact R0-numerics distance (ascending-k fp32 FMA chain)
__device__ __forceinline__ float exact_dist(const float* __restrict__ x,
                                            const float* __restrict__ w,
                                            int row, int code) {
    const float* xr = x + (size_t)row * E_DIM;
    const float* wr = w + (size_t)code * E_DIM;
    float acc = 0.f;
    #pragma unroll 8
    for (int k = 0; k < E_DIM; ++k) acc = fmaf(__ldg(xr + k), __ldg(wr + k), acc);
    return fmaf(-2.0f, acc, g_x2[row]) + g_w2[code];
}

// ---------------------------------------------------------------------------
// fused split(x, hi only) + x2 : 32 rows per block
// ---------------------------------------------------------------------------
__global__ void splitx_x2_kernel(const float* __restrict__ x) {
    __shared__ float xs[32 * E_DIM];
    const int tid = threadIdx.x;
    const int base = blockIdx.x * 32 * E_DIM;
    #pragma unroll
    for (int it = 0; it < 32; ++it) {
        int i = tid + it * 256;
        xs[i] = x[base + i];
    }
    __syncthreads();
    #pragma unroll
    for (int it = 0; it < 32; ++it) {
        int i = tid + it * 256;
        g_xh[base + i] = __float2half_rn(xs[i]);
    }
    if (tid < 32) {
        const float* r = &xs[tid * E_DIM];
        float s = 0.f;
        for (int k = 0; k < E_DIM; ++k) s = fmaf(r[k], r[k], s);
        g_x2[blockIdx.x * 32 + tid] = s;
    }
}

// ---------------------------------------------------------------------------
// fused split(w, scale 1024) + w2 : warp per code (w2 numerics == R0)
// ---------------------------------------------------------------------------
__global__ void splitw_w2_kernel(const float* __restrict__ w) {
    int code = (blockIdx.x * blockDim.x + threadIdx.x) >> 5;
    int lane = threadIdx.x & 31;
    if (code >= Q_CODES) return;
    const float* row = w + (size_t)code * E_DIM;
    float v[8];
    float s = 0.f;
    #pragma unroll
    for (int j = 0; j < 8; ++j) {
        v[j] = row[lane + 32 * j];
        s = fmaf(v[j], v[j], s);
    }
    #pragma unroll
    for (int off = 16; off; off >>= 1) s += __shfl_down_sync(0xffffffffu, s, off);
    if (lane == 0) g_w2[code] = s;
    #pragma unroll
    for (int j = 0; j < 8; ++j) {
        float sv = v[j] * 1024.0f;                 // exact
        __half h = __float2half_rn(sv);
        g_wh[(size_t)code * E_DIM + lane + 32 * j] = h;
        g_wl[(size_t)code * E_DIM + lane + 32 * j] = __float2half_rn(sv - __half2float(h));
    }
}

__global__ void reset_kernel() { if (threadIdx.x == 0) g_nflag = 0; }

// ---------------------------------------------------------------------------
// vq B chunk (hi only)
// ---------------------------------------------------------------------------
__device__ __forceinline__ void vq_issue_chunk(uint32_t smem_u, int s, int tid) {
    const int t = s >> 2, c = s & 3;
    const uint32_t bst = smem_u + ((s & 1) ? BST1_OFF : BST0_OFF);
    const __half* srcH = g_wh + (size_t)(t * BN) * E_DIM + c * KCH;
    #pragma unroll
    for (int it = 0; it < 4; ++it) {
        int i = tid + it * 256;          // 0..1023
        int row = i >> 3, q = i & 7;
        CP_ASYNC16(bst + (uint32_t)(row * BS_ROW_BYTES + q * 16),
                   (const void*)(srcH + row * E_DIM + q * 8));
    }
}

// ---------------------------------------------------------------------------
// vq pass: SINGLE-pass fp16 mma + best/second-best; writes bestI/bestD/flag
// ---------------------------------------------------------------------------
__global__ __launch_bounds__(256, 1)
void vq_kernel() {
    extern __shared__ __align__(128) char smem[];
    const uint32_t smem_u = smem_u32(smem);
    float* w2s = (float*)(smem + W2S_OFF);
    unsigned long long* sredB = (unsigned long long*)(smem + SREDB_OFF);
    unsigned int*       sredS = (unsigned int*)(smem + SREDS_OFF);

    const int tid  = threadIdx.x;
    const int lane = tid & 31;
    const int wid  = tid >> 5;
    const int wm   = wid >> 2;
    const int wn   = wid & 3;
    const int rowBase = blockIdx.x * BM;

    vq_issue_chunk(smem_u, 0, tid);
    CP_COMMIT();

    {   // resident A (hi only), row stride 528B
        const uint4* gh = (const uint4*)(g_xh + (size_t)rowBase * E_DIM);
        #pragma unroll
        for (int it = 0; it < 16; ++it) {
            int i = tid + it * 256;
            int r = i >> 5, q = i & 31;
            *(uint4*)(smem + XSH_OFF + r * 528 + q * 16) = gh[r * 32 + q];
        }
    }
    #pragma unroll
    for (int it = 0; it < 16; ++it) w2s[tid + it * 256] = g_w2[tid + it * 256];
    if (tid < BM) { sredB[tid] = 0xFFFFFFFFFFFFFFFFull; sredS[tid] = 0xFFFFFFFFu; }

    float x2r[8];
    #pragma unroll
    for (int mf = 0; mf < 4; ++mf)
        #pragma unroll
        for (int h = 0; h < 2; ++h)
            x2r[mf * 2 + h] = g_x2[rowBase + wm * 64 + mf * 16 + h * 8 + (lane >> 2)];

    float bestD[8], secD[8];
    int   bestI[8];
    #pragma unroll
    for (int i = 0; i < 8; ++i) { bestD[i] = INFINITY; secD[i] = INFINITY; bestI[i] = 0; }

    float acc[4][4][4];

    for (int t = 0; t < NTILES; ++t) {
        #pragma unroll
        for (int mf = 0; mf < 4; ++mf)
            #pragma unroll
            for (int nf = 0; nf < 4; ++nf)
                #pragma unroll
                for (int e = 0; e < 4; ++e) acc[mf][nf][e] = 0.f;

        for (int c = 0; c < NCH; ++c) {
            const int s = t * NCH + c;
            if (s + 1 < NSTEPS) { vq_issue_chunk(smem_u, s + 1, tid); CP_COMMIT(); CP_WAIT1(); }
            else                { CP_WAIT0(); }
            __syncthreads();

            const uint32_t bst = smem_u + ((s & 1) ? BST1_OFF : BST0_OFF);
            const int kglob0 = c * KCH;

            #pragma unroll
            for (int kk = 0; kk < 4; ++kk) {
                const int kg = kglob0 + kk * 16;
                const int kl = kk * 16;
                uint32_t Ah[4][4], Bh[4][2];
                #pragma unroll
                for (int mf = 0; mf < 4; ++mf) {
                    uint32_t off = (uint32_t)((wm * 64 + mf * 16 + (lane & 15)) * 528
                                              + (kg + ((lane >> 4) << 3)) * 2);
                    LDMATRIX_X4(Ah[mf][0], Ah[mf][1], Ah[mf][2], Ah[mf][3], smem_u + XSH_OFF + off);
                }
                #pragma unroll
                for (int p = 0; p < 2; ++p) {
                    uint32_t n = (uint32_t)(wn * 32 + p * 16 + (lane & 7) + ((lane >> 4) << 3));
                    uint32_t off = n * BS_ROW_BYTES + (uint32_t)((kl + (((lane >> 3) & 1) << 3)) * 2);
                    LDMATRIX_X4(Bh[p*2][0], Bh[p*2][1], Bh[p*2+1][0], Bh[p*2+1][1], bst + off);
                }
                #pragma unroll
                for (int mf = 0; mf < 4; ++mf)
                    #pragma unroll
                    for (int nf = 0; nf < 4; ++nf) mma16816(acc[mf][nf], Ah[mf], Bh[nf]);
            }
            __syncthreads();
        }

        const int codeBase = t * BN + wn * 32;
        #pragma unroll
        for (int mf = 0; mf < 4; ++mf)
            #pragma unroll
            for (int h = 0; h < 2; ++h) {
                const int slot = mf * 2 + h;
                float x2v = x2r[slot];
                float d0 = bestD[slot], d1 = secD[slot];
                int   i0 = bestI[slot];
                #pragma unroll
                for (int nf = 0; nf < 4; ++nf)
                    #pragma unroll
                    for (int j = 0; j < 2; ++j) {
                        int code  = codeBase + nf * 8 + (lane & 3) * 2 + j;
                        float dot = acc[mf][nf][h * 2 + j] * 0.0009765625f;
                        float dv  = fmaf(-2.0f, dot, x2v) + w2s[code];
                        if (dv < d0)      { d1 = d0; d0 = dv; i0 = code; }
                        else if (dv < d1) { d1 = dv; }
                    }
                bestD[slot] = d0; secD[slot] = d1; bestI[slot] = i0;
            }
    }

    __syncthreads();
    #pragma unroll
    for (int i = 0; i < 8; ++i) {
        int rowLocal = wm * 64 + (i >> 1) * 16 + (i & 1) * 8 + (lane >> 2);
        unsigned long long pack =
            ((unsigned long long)__float_as_uint(bestD[i]) << 32) | (unsigned)bestI[i];
        atomicMin(&sredB[rowLocal], pack);
    }
    __syncthreads();
    #pragma unroll
    for (int i = 0; i < 8; ++i) {
        int rowLocal = wm * 64 + (i >> 1) * 16 + (i & 1) * 8 + (lane >> 2);
        unsigned winIdx = (unsigned)(sredB[rowLocal] & 0xffffffffull);
        float cand = ((unsigned)bestI[i] == winIdx) ? secD[i] : bestD[i];
        atomicMin(&sredS[rowLocal], __float_as_uint(cand));
    }
    __syncthreads();

    if (tid < BM) {
        unsigned long long bp = sredB[tid];
        float bd = __uint_as_float((unsigned)(bp >> 32));
        float sd = __uint_as_float(sredS[tid]);
        int row = rowBase + tid;
        g_bestI[row] = (int)(bp & 0xffffffffull);
        g_bestD[row] = bd;
        g_flag[row]  = (sd - bd <= M_FLAG) ? 1 : 0;
    }
}

// ---------------------------------------------------------------------------
__global__ void compact_kernel() {
    int r = blockIdx.x * blockDim.x + threadIdx.x;
    if (r >= ROWS_TOT) return;
    if (g_flag[r]) {
        int p = atomicAdd(&g_nflag, 1);
        g_flagrows[p] = r;
        g_red[r] = 0xFFFFFFFFFFFFFFFFull;
    }
}

// copy flagged rows; recompute hi/lo split from fp32 x (identical formula)
__global__ void copyrows_kernel(const float* __restrict__ x) {
    const int nf = g_nflag;
    const int t = threadIdx.x;              // 64 threads, 4 floats each
    for (int p = blockIdx.x; p < nf; p += gridDim.x) {
        int row = g_flagrows[p];
        const float4 v4 = ((const float4*)(x + (size_t)row * E_DIM))[t];
        __half2* dh = (__half2*)(g_xh2 + (size_t)p * E_DIM) + t * 2;
        __half2* dl = (__half2*)(g_xl2 + (size_t)p * E_DIM) + t * 2;
        float f[4] = {v4.x, v4.y, v4.z, v4.w};
        __half h[4], l[4];
        #pragma unroll
        for (int j = 0; j < 4; ++j) {
            h[j] = __float2half_rn(f[j]);
            l[j] = __float2half_rn(f[j] - __half2float(h[j]));
        }
        dh[0] = __halves2half2(h[0], h[1]);
        dh[1] = __halves2half2(h[2], h[3]);
        dl[0] = __halves2half2(l[0], l[1]);
        dl[1] = __halves2half2(l[2], l[3]);
    }
}

// ---------------------------------------------------------------------------
// refine B chunk (hi + lo)
// ---------------------------------------------------------------------------
__device__ __forceinline__ void rf_issue_chunk(uint32_t smem_u, int quarter, int s, int tid) {
    const int t = s >> 2, c = s & 3;
    const int codeBase = quarter * 1024 + t * BN;
    const uint32_t bst = smem_u + ((s & 1) ? RB1_OFF : RB0_OFF);
    const __half* srcH = g_wh + (size_t)codeBase * E_DIM + c * KCH;
    const __half* srcL = g_wl + (size_t)codeBase * E_DIM + c * KCH;
    #pragma unroll
    for (int it = 0; it < 4; ++it) {
        int i = tid + it * 256;
        int row = i >> 3, q = i & 7;
        uint32_t dst = bst + (uint32_t)(row * BS_ROW_BYTES + q * 16);
        CP_ASYNC16(dst, (const void*)(srcH + row * E_DIM + q * 8));
        CP_ASYNC16(dst + B_TYPE_BYTES, (const void*)(srcL + row * E_DIM + q * 8));
    }
}

// ---------------------------------------------------------------------------
// refine: flagged rows, 3-pass fp16 mma; candidates (dv <= bestD+M) -> exact
// ---------------------------------------------------------------------------
__global__ __launch_bounds__(256, 1)
void refine_kernel(const float* __restrict__ x, const float* __restrict__ w) {
    extern __shared__ __align__(128) char smem[];
    const uint32_t smem_u = smem_u32(smem);
    float* w2q  = (float*)(smem + RW2_OFF);
    int*   srow = (int*)(smem + RROW_OFF);

    const int tid  = threadIdx.x;
    const int lane = tid & 31;
    const int wid  = tid >> 5;
    const int wm   = wid >> 2;          // 0..1 -> 16 rows each
    const int wn   = wid & 3;

    const int nflag  = g_nflag;
    const int nItems = ((nflag + 31) >> 5) * 4;

    for (int item = blockIdx.x; item < nItems; item += gridDim.x) {
        const int grp = item >> 2, quarter = item & 3;
        __syncthreads();                 // smem reuse across items

        rf_issue_chunk(smem_u, quarter, 0, tid);
        CP_COMMIT();

        #pragma unroll
        for (int it = 0; it < 4; ++it) {
            int i = tid + it * 256;      // 0..1023
            int r = i >> 5, q = i & 31;
            int p = grp * 32 + r; if (p >= nflag) p = nflag - 1;
            *(uint4*)(smem + RXH_OFF + r * 528 + q * 16) =
                ((const uint4*)(g_xh2 + (size_t)p * E_DIM))[q];
            *(uint4*)(smem + RXL_OFF + r * 528 + q * 16) =
                ((const uint4*)(g_xl2 + (size_t)p * E_DIM))[q];
        }
        #pragma unroll
        for (int it = 0; it < 4; ++it)
            w2q[tid + it * 256] = g_w2[quarter * 1024 + tid + it * 256];
        if (tid < 32) {
            int p = grp * 32 + tid; if (p >= nflag) p = nflag - 1;
            srow[tid] = g_flagrows[p];
        }
        __syncthreads();

        int   rid[2]; float x2v[2], thr[2];
        #pragma unroll
        for (int h = 0; h < 2; ++h) {
            int rl = wm * 16 + h * 8 + (lane >> 2);
            rid[h] = srow[rl];
            x2v[h] = g_x2[rid[h]];
            thr[h] = g_bestD[rid[h]] + M_COLL;
        }

        for (int t = 0; t < 8; ++t) {
            float acc[4][4];
            #pragma unroll
            for (int nf = 0; nf < 4; ++nf)
                #pragma unroll
                for (int e = 0; e < 4; ++e) acc[nf][e] = 0.f;

            for (int c = 0; c < 4; ++c) {
                const int s = t * 4 + c;
                if (s + 1 < 32) { rf_issue_chunk(smem_u, quarter, s + 1, tid); CP_COMMIT(); CP_WAIT1(); }
                else            { CP_WAIT0(); }
                __syncthreads();

                const uint32_t bst = smem_u + ((s & 1) ? RB1_OFF : RB0_OFF);
                const int kglob0 = c * KCH;

                #pragma unroll
                for (int kk = 0; kk < 4; ++kk) {
                    const int kg = kglob0 + kk * 16;
                    const int kl = kk * 16;
                    uint32_t Ah[4], Al[4], Bh[4][2], Bl[4][2];
                    {
                        uint32_t off = (uint32_t)((wm * 16 + (lane & 15)) * 528
                                                  + (kg + ((lane >> 4) << 3)) * 2);
                        LDMATRIX_X4(Ah[0], Ah[1], Ah[2], Ah[3], smem_u + RXH_OFF + off);
                        LDMATRIX_X4(Al[0], Al[1], Al[2], Al[3], smem_u + RXL_OFF + off);
                    }
                    #pragma unroll
                    for (int p = 0; p < 2; ++p) {
                        uint32_t n = (uint32_t)(wn * 32 + p * 16 + (lane & 7) + ((lane >> 4) << 3));
                        uint32_t off = n * BS_ROW_BYTES + (uint32_t)((kl + (((lane >> 3) & 1) << 3)) * 2);
                        LDMATRIX_X4(Bh[p*2][0], Bh[p*2][1], Bh[p*2+1][0], Bh[p*2+1][1], bst + off);
                        LDMATRIX_X4(Bl[p*2][0], Bl[p*2][1], Bl[p*2+1][0], Bl[p*2+1][1],
                                    bst + B_TYPE_BYTES + off);
                    }
                    #pragma unroll
                    for (int nf = 0; nf < 4; ++nf) mma16816(acc[nf], Ah, Bh[nf]);
                    #pragma unroll
                    for (int nf = 0; nf < 4; ++nf) mma16816(acc[nf], Al, Bh[nf]);
                    #pragma unroll
                    for (int nf = 0; nf < 4; ++nf) mma16816(acc[nf], Ah, Bl[nf]);
                }
                __syncthreads();
            }

            const int codeBase = quarter * 1024 + t * BN + wn * 32;
            #pragma unroll
            for (int h = 0; h < 2; ++h)
                #pragma unroll
                for (int nf = 0; nf < 4; ++nf)
                    #pragma unroll
                    for (int j = 0; j < 2; ++j) {
                        int code  = codeBase + nf * 8 + (lane & 3) * 2 + j;
                        float dot = acc[nf][h * 2 + j] * 0.0009765625f;
                        float dv  = fmaf(-2.0f, dot, x2v[h]) + w2q[t * BN + wn * 32 + nf * 8 + (lane & 3) * 2 + j];
                        if (dv <= thr[h]) {
                            float de = exact_dist(x, w, rid[h], code);
                            unsigned long long pack =
                                ((unsigned long long)__float_as_uint(de) << 32) | (unsigned)code;
                            atomicMin(&g_red[rid[h]], pack);
                        }
                    }
        }
    }
}

// ---------------------------------------------------------------------------
// gather: 4 rows per 256-thread block
// ---------------------------------------------------------------------------
__global__ void gather_kernel(const float* __restrict__ w, float* __restrict__ out,
                              float* __restrict__ out_idx_f) {
    const int t   = threadIdx.x;
    const int row = blockIdx.x * 4 + (t >> 6);
    const int q   = t & 63;
    int idx = g_flag[row] ? (int)(g_red[row] & 0xffffffffull) : g_bestI[row];
    ((float4*)(out + (size_t)row * E_DIM))[q] =
        ((const float4*)(w + (size_t)idx * E_DIM))[q];
    if (q == 0) out_idx_f[row] = (float)idx;
}

// ---------------------------------------------------------------------------
extern "C" void kernel_launch(void* const* d_in, const int* in_sizes, int n_in,
                              void* d_out, int out_size) {
    const float* x = (const float*)d_in[0];
    const float* w = (const float*)d_in[1];
    int rows = in_sizes[0] / E_DIM;        // 32768

    float* out     = (float*)d_out;
    float* out_idx = out + (size_t)rows * E_DIM;

    cudaFuncSetAttribute(vq_kernel,
                         cudaFuncAttributeMaxDynamicSharedMemorySize, VQ_SMEM);
    cudaFuncSetAttribute(refine_kernel,
                         cudaFuncAttributeMaxDynamicSharedMemorySize, RF_SMEM);

    splitx_x2_kernel<<<rows / 32, 256>>>(x);                  // 1
    splitw_w2_kernel<<<Q_CODES / 8, 256>>>(w);                // 2
    reset_kernel<<<1, 32>>>();                                // 3
    vq_kernel<<<rows / BM, 256, VQ_SMEM>>>();                 // 4  <- ncu target
    compact_kernel<<<(ROWS_TOT + 255) / 256, 256>>>();        // 5
    copyrows_kernel<<<1024, 64>>>(x);                         // 6
    refine_kernel<<<444, 256, RF_SMEM>>>(x, w);               // 7
    gather_kernel<<<rows / 4, 256>>>(w, out, out_idx);        // 8
}